// round 3
// baseline (speedup 1.0000x reference)
#include <cuda_runtime.h>
#include <math.h>

// Problem constants
#define B_ 2
#define S_ 2048
#define D_ 1024
#define H_ 16
#define DEPTH_ 64
#define M_ (B_ * S_)            // 4096 rows for projections
#define BH_ (B_ * H_)           // 32 batched heads
#define OUT_ELEMS (B_ * S_ * D_)                 // 4,194,304
#define ATTN_ELEMS ((size_t)B_ * H_ * S_ * S_)   // 134,217,728

// Scratch (allocation-free rule: __device__ globals)
__device__ float g_Qh[(size_t)BH_ * S_ * DEPTH_];   // [BH, S, 64]
__device__ float g_Kh[(size_t)BH_ * S_ * DEPTH_];
__device__ float g_Vh[(size_t)BH_ * S_ * DEPTH_];
__device__ float g_ctx[(size_t)M_ * D_];            // [B*S, 1024] (heads merged)
__device__ float g_attn_scratch[ATTN_ELEMS];        // used only if d_out lacks attn

// ---------------------------------------------------------------------------
// Projection GEMM: P = X @ W + b.   X:[M,K] W:[K,N] b:[N]
// 128x128 tile, K-chunks of 16, 256 threads, 8x8 microtile, float4 LDS.
// headsplit=1: write to [B,H,S,64]; headsplit=0: row-major [M,N].
// ---------------------------------------------------------------------------
__global__ __launch_bounds__(256) void proj_kernel(
    const float* __restrict__ X, const float* __restrict__ W,
    const float* __restrict__ bias, float* __restrict__ out,
    int M, int K, int N, int headsplit)
{
    __shared__ float As[16][128];   // K-major
    __shared__ float Bs[16][128];
    const int tid = threadIdx.x;
    const int tx = tid & 15;          // col group
    const int ty = tid >> 4;          // row group
    const int row0 = blockIdx.y * 128;
    const int col0 = blockIdx.x * 128;

    float acc[8][8];
#pragma unroll
    for (int i = 0; i < 8; i++)
#pragma unroll
        for (int j = 0; j < 8; j++) acc[i][j] = 0.f;

    for (int k0 = 0; k0 < K; k0 += 16) {
        // A tile: 128 rows x 16 k  (512 float4 loads, scatter-transpose)
#pragma unroll
        for (int i = tid; i < 512; i += 256) {
            int r = i >> 2, c4 = i & 3;
            float4 x = *(const float4*)(X + (size_t)(row0 + r) * K + k0 + c4 * 4);
            As[c4 * 4 + 0][r] = x.x;
            As[c4 * 4 + 1][r] = x.y;
            As[c4 * 4 + 2][r] = x.z;
            As[c4 * 4 + 3][r] = x.w;
        }
        // B tile: 16 k x 128 cols (512 float4 loads, direct)
#pragma unroll
        for (int i = tid; i < 512; i += 256) {
            int r = i >> 5, c4 = i & 31;
            *(float4*)&Bs[r][c4 * 4] =
                *(const float4*)(W + (size_t)(k0 + r) * N + col0 + c4 * 4);
        }
        __syncthreads();
#pragma unroll
        for (int kk = 0; kk < 16; kk++) {
            float4 a0 = *(const float4*)&As[kk][ty * 8];
            float4 a1 = *(const float4*)&As[kk][ty * 8 + 4];
            float4 b0 = *(const float4*)&Bs[kk][tx * 8];
            float4 b1 = *(const float4*)&Bs[kk][tx * 8 + 4];
            float a[8] = {a0.x, a0.y, a0.z, a0.w, a1.x, a1.y, a1.z, a1.w};
            float b[8] = {b0.x, b0.y, b0.z, b0.w, b1.x, b1.y, b1.z, b1.w};
#pragma unroll
            for (int i = 0; i < 8; i++)
#pragma unroll
                for (int j = 0; j < 8; j++) acc[i][j] += a[i] * b[j];
        }
        __syncthreads();
    }

    float4 bias0 = *(const float4*)(bias + col0 + tx * 8);
    float4 bias1 = *(const float4*)(bias + col0 + tx * 8 + 4);
#pragma unroll
    for (int i = 0; i < 8; i++) {
        int row = row0 + ty * 8 + i;
        float4 v0 = make_float4(acc[i][0] + bias0.x, acc[i][1] + bias0.y,
                                acc[i][2] + bias0.z, acc[i][3] + bias0.w);
        float4 v1 = make_float4(acc[i][4] + bias1.x, acc[i][5] + bias1.y,
                                acc[i][6] + bias1.z, acc[i][7] + bias1.w);
        int col = col0 + tx * 8;
        if (headsplit) {
            int b = row >> 11, s = row & 2047;
            int h = col >> 6, d = col & 63;
            float* dst = out + ((size_t)(b * H_ + h) * S_ + s) * DEPTH_ + d;
            *(float4*)dst = v0;
            *(float4*)(dst + 4) = v1;
        } else {
            float* dst = out + (size_t)row * N + col;
            *(float4*)dst = v0;
            *(float4*)(dst + 4) = v1;
        }
    }
}

// ---------------------------------------------------------------------------
// Logits: per bh: C = Qh[S,64] @ Kh[S,64]^T * 0.125 + mask*1e-9
// 128x128 tile, K=64 in chunks of 16. grid (16, 16, 32)
// ---------------------------------------------------------------------------
__global__ __launch_bounds__(256) void logits_kernel(
    const float* __restrict__ Qh, const float* __restrict__ Kh,
    const float* __restrict__ mask, float* __restrict__ attn)
{
    const int bh = blockIdx.z;
    const float* A = Qh + (size_t)bh * S_ * DEPTH_;
    const float* Bm = Kh + (size_t)bh * S_ * DEPTH_;
    float* C = attn + (size_t)bh * S_ * S_;
    const int bidx = bh >> 4;  // batch index for mask

    __shared__ float As[16][128];
    __shared__ float Bs[16][128];
    const int tid = threadIdx.x;
    const int tx = tid & 15;
    const int ty = tid >> 4;
    const int row0 = blockIdx.y * 128;   // q rows
    const int col0 = blockIdx.x * 128;   // k cols

    float acc[8][8];
#pragma unroll
    for (int i = 0; i < 8; i++)
#pragma unroll
        for (int j = 0; j < 8; j++) acc[i][j] = 0.f;

#pragma unroll
    for (int k0 = 0; k0 < DEPTH_; k0 += 16) {
        // Q tile: scatter-transpose
#pragma unroll
        for (int i = tid; i < 512; i += 256) {
            int r = i >> 2, c4 = i & 3;
            float4 x = *(const float4*)(A + (size_t)(row0 + r) * DEPTH_ + k0 + c4 * 4);
            As[c4 * 4 + 0][r] = x.x;
            As[c4 * 4 + 1][r] = x.y;
            As[c4 * 4 + 2][r] = x.z;
            As[c4 * 4 + 3][r] = x.w;
        }
        // K^T tile: Bs[d][kcol] — scatter-transpose from K rows
#pragma unroll
        for (int i = tid; i < 512; i += 256) {
            int r = i >> 2, c4 = i & 3;   // r = kcol-local
            float4 x = *(const float4*)(Bm + (size_t)(col0 + r) * DEPTH_ + k0 + c4 * 4);
            Bs[c4 * 4 + 0][r] = x.x;
            Bs[c4 * 4 + 1][r] = x.y;
            Bs[c4 * 4 + 2][r] = x.z;
            Bs[c4 * 4 + 3][r] = x.w;
        }
        __syncthreads();
#pragma unroll
        for (int kk = 0; kk < 16; kk++) {
            float4 a0 = *(const float4*)&As[kk][ty * 8];
            float4 a1 = *(const float4*)&As[kk][ty * 8 + 4];
            float4 b0 = *(const float4*)&Bs[kk][tx * 8];
            float4 b1 = *(const float4*)&Bs[kk][tx * 8 + 4];
            float a[8] = {a0.x, a0.y, a0.z, a0.w, a1.x, a1.y, a1.z, a1.w};
            float b[8] = {b0.x, b0.y, b0.z, b0.w, b1.x, b1.y, b1.z, b1.w};
#pragma unroll
            for (int i = 0; i < 8; i++)
#pragma unroll
                for (int j = 0; j < 8; j++) acc[i][j] += a[i] * b[j];
        }
        __syncthreads();
    }

#pragma unroll
    for (int i = 0; i < 8; i++) {
        int q = row0 + ty * 8 + i;
        int kc = col0 + tx * 8;
        const float* mrow = mask + ((size_t)bidx * S_ + q) * S_ + kc;
        float4 m0 = *(const float4*)mrow;
        float4 m1 = *(const float4*)(mrow + 4);
        float4 v0 = make_float4(acc[i][0] * 0.125f + m0.x * 1e-9f,
                                acc[i][1] * 0.125f + m0.y * 1e-9f,
                                acc[i][2] * 0.125f + m0.z * 1e-9f,
                                acc[i][3] * 0.125f + m0.w * 1e-9f);
        float4 v1 = make_float4(acc[i][4] * 0.125f + m1.x * 1e-9f,
                                acc[i][5] * 0.125f + m1.y * 1e-9f,
                                acc[i][6] * 0.125f + m1.z * 1e-9f,
                                acc[i][7] * 0.125f + m1.w * 1e-9f);
        float* dst = C + (size_t)q * S_ + kc;
        *(float4*)dst = v0;
        *(float4*)(dst + 4) = v1;
    }
}

// ---------------------------------------------------------------------------
// Row softmax over 2048 elements, in place. One block per row, 256 threads.
// ---------------------------------------------------------------------------
__global__ __launch_bounds__(256) void softmax_kernel(float* __restrict__ attn)
{
    float4* p = (float4*)(attn + (size_t)blockIdx.x * S_);
    const int tid = threadIdx.x;
    const int lane = tid & 31, warp = tid >> 5;
    __shared__ float red[8];

    float4 v0 = p[tid];
    float4 v1 = p[tid + 256];

    float m = fmaxf(fmaxf(fmaxf(v0.x, v0.y), fmaxf(v0.z, v0.w)),
                    fmaxf(fmaxf(v1.x, v1.y), fmaxf(v1.z, v1.w)));
#pragma unroll
    for (int s = 16; s > 0; s >>= 1) m = fmaxf(m, __shfl_xor_sync(~0u, m, s));
    if (lane == 0) red[warp] = m;
    __syncthreads();
    m = red[lane & 7];
#pragma unroll
    for (int s = 4; s > 0; s >>= 1) m = fmaxf(m, __shfl_xor_sync(~0u, m, s));

    v0.x = __expf(v0.x - m); v0.y = __expf(v0.y - m);
    v0.z = __expf(v0.z - m); v0.w = __expf(v0.w - m);
    v1.x = __expf(v1.x - m); v1.y = __expf(v1.y - m);
    v1.z = __expf(v1.z - m); v1.w = __expf(v1.w - m);

    float sum = (v0.x + v0.y) + (v0.z + v0.w) + (v1.x + v1.y) + (v1.z + v1.w);
#pragma unroll
    for (int s = 16; s > 0; s >>= 1) sum += __shfl_xor_sync(~0u, sum, s);
    __syncthreads();
    if (lane == 0) red[warp] = sum;
    __syncthreads();
    sum = red[lane & 7];
#pragma unroll
    for (int s = 4; s > 0; s >>= 1) sum += __shfl_xor_sync(~0u, sum, s);

    float inv = 1.f / sum;
    v0.x *= inv; v0.y *= inv; v0.z *= inv; v0.w *= inv;
    v1.x *= inv; v1.y *= inv; v1.z *= inv; v1.w *= inv;
    p[tid] = v0;
    p[tid + 256] = v1;
}

// ---------------------------------------------------------------------------
// ctx = attn[S,S] @ Vh[S,64] per bh; write merged-head layout [B*S, 1024].
// Tile: 256 q-rows x 64 cols, K-chunks of 16, 8x8 microtile. grid (8, 32).
// ---------------------------------------------------------------------------
__global__ __launch_bounds__(256) void ctx_kernel(
    const float* __restrict__ attn, const float* __restrict__ Vh,
    float* __restrict__ ctx)
{
    const int bh = blockIdx.y;
    const float* A = attn + (size_t)bh * S_ * S_;
    const float* Bm = Vh + (size_t)bh * S_ * DEPTH_;
    const int b = bh >> 4, h = bh & 15;

    __shared__ float As[16][256];
    __shared__ float Bs[16][64];
    const int tid = threadIdx.x;
    const int tx = tid & 7;           // col group (8 cols)
    const int ty = tid >> 3;          // row group (8 rows, 32 groups -> 256 rows)
    const int row0 = blockIdx.x * 256;

    float acc[8][8];
#pragma unroll
    for (int i = 0; i < 8; i++)
#pragma unroll
        for (int j = 0; j < 8; j++) acc[i][j] = 0.f;

    for (int k0 = 0; k0 < S_; k0 += 16) {
        // attn tile: 256 rows x 16 k, scatter-transpose (1024 float4 loads)
#pragma unroll
        for (int i = tid; i < 1024; i += 256) {
            int r = i >> 2, c4 = i & 3;
            float4 x = *(const float4*)(A + (size_t)(row0 + r) * S_ + k0 + c4 * 4);
            As[c4 * 4 + 0][r] = x.x;
            As[c4 * 4 + 1][r] = x.y;
            As[c4 * 4 + 2][r] = x.z;
            As[c4 * 4 + 3][r] = x.w;
        }
        // V tile: 16 k x 64 cols (256 float4 loads, direct)
        {
            int r = tid >> 4, c4 = tid & 15;
            *(float4*)&Bs[r][c4 * 4] =
                *(const float4*)(Bm + (size_t)(k0 + r) * DEPTH_ + c4 * 4);
        }
        __syncthreads();
#pragma unroll
        for (int kk = 0; kk < 16; kk++) {
            float4 a0 = *(const float4*)&As[kk][ty * 8];
            float4 a1 = *(const float4*)&As[kk][ty * 8 + 4];
            float4 b0 = *(const float4*)&Bs[kk][tx * 8];
            float4 b1 = *(const float4*)&Bs[kk][tx * 8 + 4];
            float a[8] = {a0.x, a0.y, a0.z, a0.w, a1.x, a1.y, a1.z, a1.w};
            float bb[8] = {b0.x, b0.y, b0.z, b0.w, b1.x, b1.y, b1.z, b1.w};
#pragma unroll
            for (int i = 0; i < 8; i++)
#pragma unroll
                for (int j = 0; j < 8; j++) acc[i][j] += a[i] * bb[j];
        }
        __syncthreads();
    }

#pragma unroll
    for (int i = 0; i < 8; i++) {
        int s = row0 + ty * 8 + i;
        float* dst = ctx + ((size_t)(b * S_ + s)) * D_ + h * DEPTH_ + tx * 8;
        *(float4*)dst = make_float4(acc[i][0], acc[i][1], acc[i][2], acc[i][3]);
        *(float4*)(dst + 4) = make_float4(acc[i][4], acc[i][5], acc[i][6], acc[i][7]);
    }
}

// ---------------------------------------------------------------------------
extern "C" void kernel_launch(void* const* d_in, const int* in_sizes, int n_in,
                              void* d_out, int out_size)
{
    const float* q    = (const float*)d_in[0];
    const float* k    = (const float*)d_in[1];
    const float* v    = (const float*)d_in[2];
    const float* mask = (const float*)d_in[3];
    const float* wq   = (const float*)d_in[4];
    const float* bq   = (const float*)d_in[5];
    const float* wk   = (const float*)d_in[6];
    const float* bk   = (const float*)d_in[7];
    const float* wv   = (const float*)d_in[8];
    const float* bv   = (const float*)d_in[9];
    const float* wo   = (const float*)d_in[10];
    const float* bo   = (const float*)d_in[11];

    float* out = (float*)d_out;

    // attn output location: concatenated after out if the harness buffer holds it
    float* attn;
    if ((size_t)out_size >= (size_t)OUT_ELEMS + ATTN_ELEMS) {
        attn = out + OUT_ELEMS;
    } else {
        cudaGetSymbolAddress((void**)&attn, g_attn_scratch);
    }

    float *Qh, *Kh, *Vh, *ctx;
    cudaGetSymbolAddress((void**)&Qh, g_Qh);
    cudaGetSymbolAddress((void**)&Kh, g_Kh);
    cudaGetSymbolAddress((void**)&Vh, g_Vh);
    cudaGetSymbolAddress((void**)&ctx, g_ctx);

    dim3 projGrid(D_ / 128, M_ / 128);            // (8, 32)
    proj_kernel<<<projGrid, 256>>>(q, wq, bq, Qh, M_, D_, D_, 1);
    proj_kernel<<<projGrid, 256>>>(k, wk, bk, Kh, M_, D_, D_, 1);
    proj_kernel<<<projGrid, 256>>>(v, wv, bv, Vh, M_, D_, D_, 1);

    dim3 logitsGrid(S_ / 128, S_ / 128, BH_);     // (16, 16, 32)
    logits_kernel<<<logitsGrid, 256>>>(Qh, Kh, mask, attn);

    softmax_kernel<<<BH_ * S_, 256>>>(attn);      // 65536 rows

    dim3 ctxGrid(S_ / 256, BH_);                  // (8, 32)
    ctx_kernel<<<ctxGrid, 256>>>(attn, Vh, ctx);

    proj_kernel<<<projGrid, 256>>>(ctx, wo, bo, out, M_, D_, D_, 0);
}

// round 4
// speedup vs baseline: 1.0425x; 1.0425x over previous
#include <cuda_runtime.h>
#include <math.h>

// Problem constants
#define B_ 2
#define S_ 2048
#define D_ 1024
#define H_ 16
#define DEPTH_ 64
#define M_ (B_ * S_)            // 4096 rows for projections
#define BH_ (B_ * H_)           // 32 batched heads
#define OUT_ELEMS (B_ * S_ * D_)                 // 4,194,304
#define ATTN_ELEMS ((size_t)B_ * H_ * S_ * S_)   // 134,217,728

// Scratch (allocation-free rule: __device__ globals)
__device__ float g_Qh[(size_t)BH_ * S_ * DEPTH_];   // [BH, S, 64]
__device__ float g_Kh[(size_t)BH_ * S_ * DEPTH_];
__device__ float g_Vh[(size_t)BH_ * S_ * DEPTH_];
__device__ float g_ctx[(size_t)M_ * D_];            // [B*S, 1024]
__device__ float g_attn_scratch[ATTN_ELEMS];        // used only if d_out lacks attn

// ---------------------------------------------------------------------------
// Packed dual-fp32 helpers (SASS FFMA2 — only reachable via PTX f32x2)
// ---------------------------------------------------------------------------
__device__ __forceinline__ void ffma2(unsigned long long& d,
                                      unsigned long long a,
                                      unsigned long long b) {
    asm("fma.rn.f32x2 %0, %1, %2, %0;" : "+l"(d) : "l"(a), "l"(b));
}
__device__ __forceinline__ unsigned long long bcast2(float x) {
    unsigned long long r;
    asm("mov.b64 %0, {%1, %1};" : "=l"(r) : "f"(x));
    return r;
}
__device__ __forceinline__ float2 unpack2(unsigned long long v) {
    float lo, hi;
    asm("mov.b64 {%0, %1}, %2;" : "=f"(lo), "=f"(hi) : "l"(v));
    return make_float2(lo, hi);
}

// Shared 8x8 microtile step: a-operands as floats, b-operands packed pairs.
#define MICROTILE_STEP(ACC, AV, BV0, BV1)                                    \
    _Pragma("unroll")                                                        \
    for (int i_ = 0; i_ < 8; i_++) {                                         \
        unsigned long long ap_ = bcast2(AV[i_]);                             \
        ffma2(ACC[i_][0], ap_, BV0.x);                                       \
        ffma2(ACC[i_][1], ap_, BV0.y);                                       \
        ffma2(ACC[i_][2], ap_, BV1.x);                                       \
        ffma2(ACC[i_][3], ap_, BV1.y);                                       \
    }

// ---------------------------------------------------------------------------
// Projection GEMM: P = X @ W + b.  X:[4096,1024] W:[1024,1024]
// 128x128 tile, K-chunks of 16, double-buffered, FFMA2 microtiles.
// ---------------------------------------------------------------------------
__global__ __launch_bounds__(256, 2) void proj_kernel(
    const float* __restrict__ X, const float* __restrict__ W,
    const float* __restrict__ bias, float* __restrict__ out, int headsplit)
{
    __shared__ float As[2][16][128];   // K-major
    __shared__ float Bs[2][16][128];
    const int tid = threadIdx.x;
    const int tx = tid & 15, ty = tid >> 4;
    const int row0 = blockIdx.y * 128, col0 = blockIdx.x * 128;

    const int ar = tid >> 2, ac = (tid & 3) * 4;   // A fill: 2 rows (ar, ar+64)
    const int br = tid >> 5, bc = (tid & 31) * 4;  // B fill: 2 rows (br, br+8)

    unsigned long long acc[8][4];
#pragma unroll
    for (int i = 0; i < 8; i++)
#pragma unroll
        for (int j = 0; j < 4; j++) acc[i][j] = 0ull;

    float4 pa0, pa1, pb0, pb1;
    // prefetch chunk 0
    pa0 = *(const float4*)(X + (size_t)(row0 + ar) * D_ + ac);
    pa1 = *(const float4*)(X + (size_t)(row0 + ar + 64) * D_ + ac);
    pb0 = *(const float4*)(W + (size_t)br * D_ + col0 + bc);
    pb1 = *(const float4*)(W + (size_t)(br + 8) * D_ + col0 + bc);
    As[0][ac + 0][ar] = pa0.x; As[0][ac + 1][ar] = pa0.y;
    As[0][ac + 2][ar] = pa0.z; As[0][ac + 3][ar] = pa0.w;
    As[0][ac + 0][ar + 64] = pa1.x; As[0][ac + 1][ar + 64] = pa1.y;
    As[0][ac + 2][ar + 64] = pa1.z; As[0][ac + 3][ar + 64] = pa1.w;
    *(float4*)&Bs[0][br][bc] = pb0;
    *(float4*)&Bs[0][br + 8][bc] = pb1;
    __syncthreads();

    const int nc = D_ / 16;   // 64
    for (int c = 0; c < nc; c++) {
        const int cur = c & 1;
        if (c + 1 < nc) {
            const int k0 = (c + 1) * 16;
            pa0 = *(const float4*)(X + (size_t)(row0 + ar) * D_ + k0 + ac);
            pa1 = *(const float4*)(X + (size_t)(row0 + ar + 64) * D_ + k0 + ac);
            pb0 = *(const float4*)(W + (size_t)(k0 + br) * D_ + col0 + bc);
            pb1 = *(const float4*)(W + (size_t)(k0 + br + 8) * D_ + col0 + bc);
        }
#pragma unroll
        for (int kk = 0; kk < 16; kk++) {
            float4 a0 = *(const float4*)&As[cur][kk][ty * 8];
            float4 a1 = *(const float4*)&As[cur][kk][ty * 8 + 4];
            ulonglong2 bv0 = *(const ulonglong2*)&Bs[cur][kk][tx * 8];
            ulonglong2 bv1 = *(const ulonglong2*)&Bs[cur][kk][tx * 8 + 4];
            float av[8] = {a0.x, a0.y, a0.z, a0.w, a1.x, a1.y, a1.z, a1.w};
            MICROTILE_STEP(acc, av, bv0, bv1);
        }
        if (c + 1 < nc) {
            const int nxt = 1 - cur;
            As[nxt][ac + 0][ar] = pa0.x; As[nxt][ac + 1][ar] = pa0.y;
            As[nxt][ac + 2][ar] = pa0.z; As[nxt][ac + 3][ar] = pa0.w;
            As[nxt][ac + 0][ar + 64] = pa1.x; As[nxt][ac + 1][ar + 64] = pa1.y;
            As[nxt][ac + 2][ar + 64] = pa1.z; As[nxt][ac + 3][ar + 64] = pa1.w;
            *(float4*)&Bs[nxt][br][bc] = pb0;
            *(float4*)&Bs[nxt][br + 8][bc] = pb1;
        }
        __syncthreads();
    }

    float4 bias0 = *(const float4*)(bias + col0 + tx * 8);
    float4 bias1 = *(const float4*)(bias + col0 + tx * 8 + 4);
#pragma unroll
    for (int i = 0; i < 8; i++) {
        float2 c0 = unpack2(acc[i][0]), c1 = unpack2(acc[i][1]);
        float2 c2 = unpack2(acc[i][2]), c3 = unpack2(acc[i][3]);
        float4 v0 = make_float4(c0.x + bias0.x, c0.y + bias0.y,
                                c1.x + bias0.z, c1.y + bias0.w);
        float4 v1 = make_float4(c2.x + bias1.x, c2.y + bias1.y,
                                c3.x + bias1.z, c3.y + bias1.w);
        int row = row0 + ty * 8 + i;
        int col = col0 + tx * 8;
        if (headsplit) {
            int b = row >> 11, s = row & 2047;
            int h = col >> 6, d = col & 63;
            float* dst = out + ((size_t)(b * H_ + h) * S_ + s) * DEPTH_ + d;
            *(float4*)dst = v0;
            *(float4*)(dst + 4) = v1;
        } else {
            float* dst = out + (size_t)row * D_ + col;
            *(float4*)dst = v0;
            *(float4*)(dst + 4) = v1;
        }
    }
}

// ---------------------------------------------------------------------------
// Logits: per bh: C = Qh[S,64] @ Kh[S,64]^T * 0.125 + mask*1e-9
// 128x128 tile, K=64 in 4 chunks of 16, double-buffered, FFMA2.
// ---------------------------------------------------------------------------
__global__ __launch_bounds__(256, 2) void logits_kernel(
    const float* __restrict__ Qh, const float* __restrict__ Kh,
    const float* __restrict__ mask, float* __restrict__ attn)
{
    const int bh = blockIdx.z;
    const float* A = Qh + (size_t)bh * S_ * DEPTH_;
    const float* Bm = Kh + (size_t)bh * S_ * DEPTH_;
    float* C = attn + (size_t)bh * S_ * S_;
    const int bidx = bh >> 4;

    __shared__ float As[2][16][128];
    __shared__ float Bs[2][16][128];
    const int tid = threadIdx.x;
    const int tx = tid & 15, ty = tid >> 4;
    const int row0 = blockIdx.y * 128;   // q rows
    const int col0 = blockIdx.x * 128;   // k cols

    const int ar = tid >> 2, ac = (tid & 3) * 4;

    unsigned long long acc[8][4];
#pragma unroll
    for (int i = 0; i < 8; i++)
#pragma unroll
        for (int j = 0; j < 4; j++) acc[i][j] = 0ull;

    float4 pa0, pa1, pb0, pb1;
    pa0 = *(const float4*)(A + (size_t)(row0 + ar) * DEPTH_ + ac);
    pa1 = *(const float4*)(A + (size_t)(row0 + ar + 64) * DEPTH_ + ac);
    pb0 = *(const float4*)(Bm + (size_t)(col0 + ar) * DEPTH_ + ac);
    pb1 = *(const float4*)(Bm + (size_t)(col0 + ar + 64) * DEPTH_ + ac);
    As[0][ac + 0][ar] = pa0.x; As[0][ac + 1][ar] = pa0.y;
    As[0][ac + 2][ar] = pa0.z; As[0][ac + 3][ar] = pa0.w;
    As[0][ac + 0][ar + 64] = pa1.x; As[0][ac + 1][ar + 64] = pa1.y;
    As[0][ac + 2][ar + 64] = pa1.z; As[0][ac + 3][ar + 64] = pa1.w;
    Bs[0][ac + 0][ar] = pb0.x; Bs[0][ac + 1][ar] = pb0.y;
    Bs[0][ac + 2][ar] = pb0.z; Bs[0][ac + 3][ar] = pb0.w;
    Bs[0][ac + 0][ar + 64] = pb1.x; Bs[0][ac + 1][ar + 64] = pb1.y;
    Bs[0][ac + 2][ar + 64] = pb1.z; Bs[0][ac + 3][ar + 64] = pb1.w;
    __syncthreads();

    const int nc = DEPTH_ / 16;   // 4
#pragma unroll
    for (int c = 0; c < nc; c++) {
        const int cur = c & 1;
        if (c + 1 < nc) {
            const int k0 = (c + 1) * 16;
            pa0 = *(const float4*)(A + (size_t)(row0 + ar) * DEPTH_ + k0 + ac);
            pa1 = *(const float4*)(A + (size_t)(row0 + ar + 64) * DEPTH_ + k0 + ac);
            pb0 = *(const float4*)(Bm + (size_t)(col0 + ar) * DEPTH_ + k0 + ac);
            pb1 = *(const float4*)(Bm + (size_t)(col0 + ar + 64) * DEPTH_ + k0 + ac);
        }
#pragma unroll
        for (int kk = 0; kk < 16; kk++) {
            float4 a0 = *(const float4*)&As[cur][kk][ty * 8];
            float4 a1 = *(const float4*)&As[cur][kk][ty * 8 + 4];
            ulonglong2 bv0 = *(const ulonglong2*)&Bs[cur][kk][tx * 8];
            ulonglong2 bv1 = *(const ulonglong2*)&Bs[cur][kk][tx * 8 + 4];
            float av[8] = {a0.x, a0.y, a0.z, a0.w, a1.x, a1.y, a1.z, a1.w};
            MICROTILE_STEP(acc, av, bv0, bv1);
        }
        if (c + 1 < nc) {
            const int nxt = 1 - cur;
            As[nxt][ac + 0][ar] = pa0.x; As[nxt][ac + 1][ar] = pa0.y;
            As[nxt][ac + 2][ar] = pa0.z; As[nxt][ac + 3][ar] = pa0.w;
            As[nxt][ac + 0][ar + 64] = pa1.x; As[nxt][ac + 1][ar + 64] = pa1.y;
            As[nxt][ac + 2][ar + 64] = pa1.z; As[nxt][ac + 3][ar + 64] = pa1.w;
            Bs[nxt][ac + 0][ar] = pb0.x; Bs[nxt][ac + 1][ar] = pb0.y;
            Bs[nxt][ac + 2][ar] = pb0.z; Bs[nxt][ac + 3][ar] = pb0.w;
            Bs[nxt][ac + 0][ar + 64] = pb1.x; Bs[nxt][ac + 1][ar + 64] = pb1.y;
            Bs[nxt][ac + 2][ar + 64] = pb1.z; Bs[nxt][ac + 3][ar + 64] = pb1.w;
        }
        __syncthreads();
    }

#pragma unroll
    for (int i = 0; i < 8; i++) {
        int q = row0 + ty * 8 + i;
        int kc = col0 + tx * 8;
        const float* mrow = mask + ((size_t)bidx * S_ + q) * S_ + kc;
        float4 m0 = *(const float4*)mrow;
        float4 m1 = *(const float4*)(mrow + 4);
        float2 c0 = unpack2(acc[i][0]), c1 = unpack2(acc[i][1]);
        float2 c2 = unpack2(acc[i][2]), c3 = unpack2(acc[i][3]);
        float4 v0 = make_float4(c0.x * 0.125f + m0.x * 1e-9f,
                                c0.y * 0.125f + m0.y * 1e-9f,
                                c1.x * 0.125f + m0.z * 1e-9f,
                                c1.y * 0.125f + m0.w * 1e-9f);
        float4 v1 = make_float4(c2.x * 0.125f + m1.x * 1e-9f,
                                c2.y * 0.125f + m1.y * 1e-9f,
                                c3.x * 0.125f + m1.z * 1e-9f,
                                c3.y * 0.125f + m1.w * 1e-9f);
        float* dst = C + (size_t)q * S_ + kc;
        *(float4*)dst = v0;
        *(float4*)(dst + 4) = v1;
    }
}

// ---------------------------------------------------------------------------
// Row softmax over 2048 elements, in place. One block per row, 256 threads.
// ---------------------------------------------------------------------------
__global__ __launch_bounds__(256) void softmax_kernel(float* __restrict__ attn)
{
    float4* p = (float4*)(attn + (size_t)blockIdx.x * S_);
    const int tid = threadIdx.x;
    const int lane = tid & 31, warp = tid >> 5;
    __shared__ float red[8];

    float4 v0 = p[tid];
    float4 v1 = p[tid + 256];

    float m = fmaxf(fmaxf(fmaxf(v0.x, v0.y), fmaxf(v0.z, v0.w)),
                    fmaxf(fmaxf(v1.x, v1.y), fmaxf(v1.z, v1.w)));
#pragma unroll
    for (int s = 16; s > 0; s >>= 1) m = fmaxf(m, __shfl_xor_sync(~0u, m, s));
    if (lane == 0) red[warp] = m;
    __syncthreads();
    m = red[lane & 7];
#pragma unroll
    for (int s = 4; s > 0; s >>= 1) m = fmaxf(m, __shfl_xor_sync(~0u, m, s));

    v0.x = __expf(v0.x - m); v0.y = __expf(v0.y - m);
    v0.z = __expf(v0.z - m); v0.w = __expf(v0.w - m);
    v1.x = __expf(v1.x - m); v1.y = __expf(v1.y - m);
    v1.z = __expf(v1.z - m); v1.w = __expf(v1.w - m);

    float sum = (v0.x + v0.y) + (v0.z + v0.w) + (v1.x + v1.y) + (v1.z + v1.w);
#pragma unroll
    for (int s = 16; s > 0; s >>= 1) sum += __shfl_xor_sync(~0u, sum, s);
    __syncthreads();
    if (lane == 0) red[warp] = sum;
    __syncthreads();
    sum = red[lane & 7];
#pragma unroll
    for (int s = 4; s > 0; s >>= 1) sum += __shfl_xor_sync(~0u, sum, s);

    float inv = 1.f / sum;
    v0.x *= inv; v0.y *= inv; v0.z *= inv; v0.w *= inv;
    v1.x *= inv; v1.y *= inv; v1.z *= inv; v1.w *= inv;
    p[tid] = v0;
    p[tid + 256] = v1;
}

// ---------------------------------------------------------------------------
// ctx = attn[S,S] @ Vh[S,64] per bh; write merged-head layout [B*S, 1024].
// 256x64 tile, K-chunks of 16, double-buffered, FFMA2. grid (8, 32).
// ---------------------------------------------------------------------------
__global__ __launch_bounds__(256, 2) void ctx_kernel(
    const float* __restrict__ attn, const float* __restrict__ Vh,
    float* __restrict__ ctx)
{
    const int bh = blockIdx.y;
    const float* A = attn + (size_t)bh * S_ * S_;
    const float* Bm = Vh + (size_t)bh * S_ * DEPTH_;
    const int b = bh >> 4, h = bh & 15;

    __shared__ float As[2][16][256];
    __shared__ float Bs[2][16][64];
    const int tid = threadIdx.x;
    const int tx = tid & 7;           // col group (8 cols)
    const int ty = tid >> 3;          // row group (8 rows x 32 -> 256 rows)
    const int row0 = blockIdx.x * 256;

    const int ar = tid >> 2, ac = (tid & 3) * 4;   // A rows ar + 64*t
    const int vr = tid >> 4, vc = (tid & 15) * 4;  // V fill

    unsigned long long acc[8][4];
#pragma unroll
    for (int i = 0; i < 8; i++)
#pragma unroll
        for (int j = 0; j < 4; j++) acc[i][j] = 0ull;

    float4 pa[4], pv;
#pragma unroll
    for (int t = 0; t < 4; t++)
        pa[t] = *(const float4*)(A + (size_t)(row0 + ar + 64 * t) * S_ + ac);
    pv = *(const float4*)(Bm + (size_t)vr * DEPTH_ + vc);
#pragma unroll
    for (int t = 0; t < 4; t++) {
        As[0][ac + 0][ar + 64 * t] = pa[t].x;
        As[0][ac + 1][ar + 64 * t] = pa[t].y;
        As[0][ac + 2][ar + 64 * t] = pa[t].z;
        As[0][ac + 3][ar + 64 * t] = pa[t].w;
    }
    *(float4*)&Bs[0][vr][vc] = pv;
    __syncthreads();

    const int nc = S_ / 16;   // 128
    for (int c = 0; c < nc; c++) {
        const int cur = c & 1;
        if (c + 1 < nc) {
            const int k0 = (c + 1) * 16;
#pragma unroll
            for (int t = 0; t < 4; t++)
                pa[t] = *(const float4*)(A + (size_t)(row0 + ar + 64 * t) * S_ + k0 + ac);
            pv = *(const float4*)(Bm + (size_t)(k0 + vr) * DEPTH_ + vc);
        }
#pragma unroll
        for (int kk = 0; kk < 16; kk++) {
            float4 a0 = *(const float4*)&As[cur][kk][ty * 8];
            float4 a1 = *(const float4*)&As[cur][kk][ty * 8 + 4];
            ulonglong2 bv0 = *(const ulonglong2*)&Bs[cur][kk][tx * 8];
            ulonglong2 bv1 = *(const ulonglong2*)&Bs[cur][kk][tx * 8 + 4];
            float av[8] = {a0.x, a0.y, a0.z, a0.w, a1.x, a1.y, a1.z, a1.w};
            MICROTILE_STEP(acc, av, bv0, bv1);
        }
        if (c + 1 < nc) {
            const int nxt = 1 - cur;
#pragma unroll
            for (int t = 0; t < 4; t++) {
                As[nxt][ac + 0][ar + 64 * t] = pa[t].x;
                As[nxt][ac + 1][ar + 64 * t] = pa[t].y;
                As[nxt][ac + 2][ar + 64 * t] = pa[t].z;
                As[nxt][ac + 3][ar + 64 * t] = pa[t].w;
            }
            *(float4*)&Bs[nxt][vr][vc] = pv;
        }
        __syncthreads();
    }

#pragma unroll
    for (int i = 0; i < 8; i++) {
        int s = row0 + ty * 8 + i;
        float2 c0 = unpack2(acc[i][0]), c1 = unpack2(acc[i][1]);
        float2 c2 = unpack2(acc[i][2]), c3 = unpack2(acc[i][3]);
        float* dst = ctx + ((size_t)(b * S_ + s)) * D_ + h * DEPTH_ + tx * 8;
        *(float4*)dst = make_float4(c0.x, c0.y, c1.x, c1.y);
        *(float4*)(dst + 4) = make_float4(c2.x, c2.y, c3.x, c3.y);
    }
}

// ---------------------------------------------------------------------------
extern "C" void kernel_launch(void* const* d_in, const int* in_sizes, int n_in,
                              void* d_out, int out_size)
{
    const float* q    = (const float*)d_in[0];
    const float* k    = (const float*)d_in[1];
    const float* v    = (const float*)d_in[2];
    const float* mask = (const float*)d_in[3];
    const float* wq   = (const float*)d_in[4];
    const float* bq   = (const float*)d_in[5];
    const float* wk   = (const float*)d_in[6];
    const float* bk   = (const float*)d_in[7];
    const float* wv   = (const float*)d_in[8];
    const float* bv   = (const float*)d_in[9];
    const float* wo   = (const float*)d_in[10];
    const float* bo   = (const float*)d_in[11];

    float* out = (float*)d_out;

    float* attn;
    if ((size_t)out_size >= (size_t)OUT_ELEMS + ATTN_ELEMS) {
        attn = out + OUT_ELEMS;
    } else {
        cudaGetSymbolAddress((void**)&attn, g_attn_scratch);
    }

    float *Qh, *Kh, *Vh, *ctx;
    cudaGetSymbolAddress((void**)&Qh, g_Qh);
    cudaGetSymbolAddress((void**)&Kh, g_Kh);
    cudaGetSymbolAddress((void**)&Vh, g_Vh);
    cudaGetSymbolAddress((void**)&ctx, g_ctx);

    dim3 projGrid(D_ / 128, M_ / 128);            // (8, 32)
    proj_kernel<<<projGrid, 256>>>(q, wq, bq, Qh, 1);
    proj_kernel<<<projGrid, 256>>>(k, wk, bk, Kh, 1);
    proj_kernel<<<projGrid, 256>>>(v, wv, bv, Vh, 1);

    dim3 logitsGrid(S_ / 128, S_ / 128, BH_);     // (16, 16, 32)
    logits_kernel<<<logitsGrid, 256>>>(Qh, Kh, mask, attn);

    softmax_kernel<<<BH_ * S_, 256>>>(attn);      // 65536 rows

    dim3 ctxGrid(S_ / 256, BH_);                  // (8, 32)
    ctx_kernel<<<ctxGrid, 256>>>(attn, Vh, ctx);

    proj_kernel<<<projGrid, 256>>>(ctx, wo, bo, out, 0);
}

// round 5
// speedup vs baseline: 1.7346x; 1.6639x over previous
#include <cuda_runtime.h>
#include <math.h>

// Problem constants
#define B_ 2
#define S_ 2048
#define D_ 1024
#define H_ 16
#define DEPTH_ 64
#define M_ (B_ * S_)            // 4096
#define BH_ (B_ * H_)           // 32
#define OUT_ELEMS (B_ * S_ * D_)
#define ATTN_ELEMS ((size_t)BH_ * S_ * S_)

// Scratch
__device__ float g_Qh[(size_t)BH_ * S_ * DEPTH_];
__device__ float g_Kh[(size_t)BH_ * S_ * DEPTH_];
__device__ float g_Vh[(size_t)BH_ * S_ * DEPTH_];
__device__ float g_ctx[(size_t)M_ * D_];
__device__ float g_attn_scratch[ATTN_ELEMS];

// ---------------------------------------------------------------------------
// tf32 helpers
// ---------------------------------------------------------------------------
__device__ __forceinline__ float f2tf(float x) {
    unsigned r; asm("cvt.rna.tf32.f32 %0, %1;" : "=r"(r) : "f"(x));
    return __uint_as_float(r);
}
__device__ __forceinline__ void mma_tf32(
    float& c0, float& c1, float& c2, float& c3,
    unsigned a0, unsigned a1, unsigned a2, unsigned a3,
    unsigned b0, unsigned b1)
{
    asm volatile(
        "mma.sync.aligned.m16n8k8.row.col.f32.tf32.tf32.f32 "
        "{%0,%1,%2,%3}, {%4,%5,%6,%7}, {%8,%9}, {%0,%1,%2,%3};"
        : "+f"(c0), "+f"(c1), "+f"(c2), "+f"(c3)
        : "r"(a0), "r"(a1), "r"(a2), "r"(a3), "r"(b0), "r"(b1));
}
#define U(x) __float_as_uint(x)

// ---------------------------------------------------------------------------
// Projection GEMM: P = X @ W + b.  X:[4096,1024] W:[1024,1024] (K-major rows)
// CTA 128x128, BK=16 double-buffered, 8 warps (2m x 4n), warp 64x32.
// ---------------------------------------------------------------------------
__global__ __launch_bounds__(256, 2) void proj_kernel(
    const float* __restrict__ X, const float* __restrict__ W,
    const float* __restrict__ bias, float* __restrict__ out, int headsplit)
{
    __shared__ float As[2][128][20];   // [m][k], pad to 20
    __shared__ float Bs[2][128][20];   // [n][k]
    const int tid = threadIdx.x, lane = tid & 31, wid = tid >> 5;
    const int wm = wid & 1, wn = wid >> 1;
    const int row0 = blockIdx.y * 128, col0 = blockIdx.x * 128;

    const int far = tid >> 2, fac = (tid & 3) * 4;   // A rows far, far+64
    const int fwk = tid >> 5, fwn = (tid & 31) * 4;  // W k-rows fwk, fwk+8

    float acc[4][4][4];
#pragma unroll
    for (int mi = 0; mi < 4; mi++)
#pragma unroll
        for (int ni = 0; ni < 4; ni++)
#pragma unroll
            for (int t = 0; t < 4; t++) acc[mi][ni][t] = 0.f;

    float4 pa0, pa1, pw0, pw1;
    pa0 = *(const float4*)(X + (size_t)(row0 + far) * D_ + fac);
    pa1 = *(const float4*)(X + (size_t)(row0 + far + 64) * D_ + fac);
    pw0 = *(const float4*)(W + (size_t)fwk * D_ + col0 + fwn);
    pw1 = *(const float4*)(W + (size_t)(fwk + 8) * D_ + col0 + fwn);
    {
        float* a = &As[0][far][fac];
        a[0] = f2tf(pa0.x); a[1] = f2tf(pa0.y); a[2] = f2tf(pa0.z); a[3] = f2tf(pa0.w);
        float* a2 = &As[0][far + 64][fac];
        a2[0] = f2tf(pa1.x); a2[1] = f2tf(pa1.y); a2[2] = f2tf(pa1.z); a2[3] = f2tf(pa1.w);
        Bs[0][fwn + 0][fwk] = f2tf(pw0.x); Bs[0][fwn + 1][fwk] = f2tf(pw0.y);
        Bs[0][fwn + 2][fwk] = f2tf(pw0.z); Bs[0][fwn + 3][fwk] = f2tf(pw0.w);
        Bs[0][fwn + 0][fwk + 8] = f2tf(pw1.x); Bs[0][fwn + 1][fwk + 8] = f2tf(pw1.y);
        Bs[0][fwn + 2][fwk + 8] = f2tf(pw1.z); Bs[0][fwn + 3][fwk + 8] = f2tf(pw1.w);
    }
    __syncthreads();

    const int nc = D_ / 16;   // 64
    for (int c = 0; c < nc; c++) {
        const int cur = c & 1;
        if (c + 1 < nc) {
            const int k0 = (c + 1) * 16;
            pa0 = *(const float4*)(X + (size_t)(row0 + far) * D_ + k0 + fac);
            pa1 = *(const float4*)(X + (size_t)(row0 + far + 64) * D_ + k0 + fac);
            pw0 = *(const float4*)(W + (size_t)(k0 + fwk) * D_ + col0 + fwn);
            pw1 = *(const float4*)(W + (size_t)(k0 + fwk + 8) * D_ + col0 + fwn);
        }
#pragma unroll
        for (int ks = 0; ks < 2; ks++) {
            unsigned af[4][4], bf[4][2];
#pragma unroll
            for (int mi = 0; mi < 4; mi++) {
                const float* p = &As[cur][wm * 64 + mi * 16 + (lane >> 2)][ks * 8 + (lane & 3)];
                af[mi][0] = U(p[0]); af[mi][1] = U(p[8 * 20]);
                af[mi][2] = U(p[4]); af[mi][3] = U(p[8 * 20 + 4]);
            }
#pragma unroll
            for (int ni = 0; ni < 4; ni++) {
                const float* p = &Bs[cur][wn * 32 + ni * 8 + (lane >> 2)][ks * 8 + (lane & 3)];
                bf[ni][0] = U(p[0]); bf[ni][1] = U(p[4]);
            }
#pragma unroll
            for (int mi = 0; mi < 4; mi++)
#pragma unroll
                for (int ni = 0; ni < 4; ni++)
                    mma_tf32(acc[mi][ni][0], acc[mi][ni][1], acc[mi][ni][2], acc[mi][ni][3],
                             af[mi][0], af[mi][1], af[mi][2], af[mi][3],
                             bf[ni][0], bf[ni][1]);
        }
        if (c + 1 < nc) {
            const int nxt = 1 - cur;
            float* a = &As[nxt][far][fac];
            a[0] = f2tf(pa0.x); a[1] = f2tf(pa0.y); a[2] = f2tf(pa0.z); a[3] = f2tf(pa0.w);
            float* a2 = &As[nxt][far + 64][fac];
            a2[0] = f2tf(pa1.x); a2[1] = f2tf(pa1.y); a2[2] = f2tf(pa1.z); a2[3] = f2tf(pa1.w);
            Bs[nxt][fwn + 0][fwk] = f2tf(pw0.x); Bs[nxt][fwn + 1][fwk] = f2tf(pw0.y);
            Bs[nxt][fwn + 2][fwk] = f2tf(pw0.z); Bs[nxt][fwn + 3][fwk] = f2tf(pw0.w);
            Bs[nxt][fwn + 0][fwk + 8] = f2tf(pw1.x); Bs[nxt][fwn + 1][fwk + 8] = f2tf(pw1.y);
            Bs[nxt][fwn + 2][fwk + 8] = f2tf(pw1.z); Bs[nxt][fwn + 3][fwk + 8] = f2tf(pw1.w);
        }
        __syncthreads();
    }

#pragma unroll
    for (int mi = 0; mi < 4; mi++) {
#pragma unroll
        for (int ni = 0; ni < 4; ni++) {
            int r = row0 + wm * 64 + mi * 16 + (lane >> 2);
            int cc = col0 + wn * 32 + ni * 8 + (lane & 3) * 2;
            float2 bb = *(const float2*)(bias + cc);
            float2 v0 = make_float2(acc[mi][ni][0] + bb.x, acc[mi][ni][1] + bb.y);
            float2 v1 = make_float2(acc[mi][ni][2] + bb.x, acc[mi][ni][3] + bb.y);
            if (headsplit) {
                int b = r >> 11, s = r & 2047;
                int h = cc >> 6, d = cc & 63;
                float* dst = out + ((size_t)(b * H_ + h) * S_ + s) * DEPTH_ + d;
                *(float2*)dst = v0;
                *(float2*)(dst + 8 * DEPTH_) = v1;   // row r+8, same b (s+8 < 2048 boundary safe: s = r&2047, r+8 within same 128-tile, s<2040+8 ok)
            } else {
                float* dst = out + (size_t)r * D_ + cc;
                *(float2*)dst = v0;
                *(float2*)(dst + 8 * D_) = v1;
            }
        }
    }
}

// ---------------------------------------------------------------------------
// Logits: per bh: C = Qh[S,64] @ Kh[S,64]^T * 0.125 + mask*1e-9
// CTA 128x128, full K=64 staged once. 8 warps (2m x 4n), warp 64x32.
// Dynamic smem: 2 * 128 * 68 floats.
// ---------------------------------------------------------------------------
__global__ __launch_bounds__(256, 2) void logits_kernel(
    const float* __restrict__ Qh, const float* __restrict__ Kh,
    const float* __restrict__ mask, float* __restrict__ attn)
{
    extern __shared__ float sm[];
    float (*As)[68] = (float(*)[68])sm;             // [q][d]
    float (*Bs)[68] = (float(*)[68])(sm + 128 * 68); // [k][d]

    const int bh = blockIdx.z;
    const float* A = Qh + (size_t)bh * S_ * DEPTH_;
    const float* Bm = Kh + (size_t)bh * S_ * DEPTH_;
    float* C = attn + (size_t)bh * S_ * S_;
    const int bidx = bh >> 4;

    const int tid = threadIdx.x, lane = tid & 31, wid = tid >> 5;
    const int wm = wid & 1, wn = wid >> 1;
    const int row0 = blockIdx.y * 128, col0 = blockIdx.x * 128;

#pragma unroll
    for (int t = 0; t < 8; t++) {
        int idx = tid + t * 256;
        int r = idx >> 4, cc = (idx & 15) * 4;
        float4 x = *(const float4*)(A + (size_t)(row0 + r) * DEPTH_ + cc);
        float* d = &As[r][cc];
        d[0] = f2tf(x.x); d[1] = f2tf(x.y); d[2] = f2tf(x.z); d[3] = f2tf(x.w);
        float4 y = *(const float4*)(Bm + (size_t)(col0 + r) * DEPTH_ + cc);
        float* e = &Bs[r][cc];
        e[0] = f2tf(y.x); e[1] = f2tf(y.y); e[2] = f2tf(y.z); e[3] = f2tf(y.w);
    }
    __syncthreads();

    float acc[4][4][4];
#pragma unroll
    for (int mi = 0; mi < 4; mi++)
#pragma unroll
        for (int ni = 0; ni < 4; ni++)
#pragma unroll
            for (int t = 0; t < 4; t++) acc[mi][ni][t] = 0.f;

#pragma unroll
    for (int ks = 0; ks < 8; ks++) {
        unsigned af[4][4], bf[4][2];
#pragma unroll
        for (int mi = 0; mi < 4; mi++) {
            const float* p = &As[wm * 64 + mi * 16 + (lane >> 2)][ks * 8 + (lane & 3)];
            af[mi][0] = U(p[0]); af[mi][1] = U(p[8 * 68]);
            af[mi][2] = U(p[4]); af[mi][3] = U(p[8 * 68 + 4]);
        }
#pragma unroll
        for (int ni = 0; ni < 4; ni++) {
            const float* p = &Bs[wn * 32 + ni * 8 + (lane >> 2)][ks * 8 + (lane & 3)];
            bf[ni][0] = U(p[0]); bf[ni][1] = U(p[4]);
        }
#pragma unroll
        for (int mi = 0; mi < 4; mi++)
#pragma unroll
            for (int ni = 0; ni < 4; ni++)
                mma_tf32(acc[mi][ni][0], acc[mi][ni][1], acc[mi][ni][2], acc[mi][ni][3],
                         af[mi][0], af[mi][1], af[mi][2], af[mi][3],
                         bf[ni][0], bf[ni][1]);
    }

#pragma unroll
    for (int mi = 0; mi < 4; mi++) {
#pragma unroll
        for (int ni = 0; ni < 4; ni++) {
            int q = row0 + wm * 64 + mi * 16 + (lane >> 2);
            int kc = col0 + wn * 32 + ni * 8 + (lane & 3) * 2;
            const float* mrow = mask + ((size_t)bidx * S_ + q) * S_ + kc;
            float2 m0 = *(const float2*)mrow;
            float2 m1 = *(const float2*)(mrow + 8 * S_);
            float* dst = C + (size_t)q * S_ + kc;
            *(float2*)dst = make_float2(acc[mi][ni][0] * 0.125f + m0.x * 1e-9f,
                                        acc[mi][ni][1] * 0.125f + m0.y * 1e-9f);
            *(float2*)(dst + 8 * S_) = make_float2(acc[mi][ni][2] * 0.125f + m1.x * 1e-9f,
                                                   acc[mi][ni][3] * 0.125f + m1.y * 1e-9f);
        }
    }
}

// ---------------------------------------------------------------------------
// Row softmax over 2048 elements, in place.
// ---------------------------------------------------------------------------
__global__ __launch_bounds__(256) void softmax_kernel(float* __restrict__ attn)
{
    float4* p = (float4*)(attn + (size_t)blockIdx.x * S_);
    const int tid = threadIdx.x;
    const int lane = tid & 31, warp = tid >> 5;
    __shared__ float red[8];

    float4 v0 = p[tid];
    float4 v1 = p[tid + 256];

    float m = fmaxf(fmaxf(fmaxf(v0.x, v0.y), fmaxf(v0.z, v0.w)),
                    fmaxf(fmaxf(v1.x, v1.y), fmaxf(v1.z, v1.w)));
#pragma unroll
    for (int s = 16; s > 0; s >>= 1) m = fmaxf(m, __shfl_xor_sync(~0u, m, s));
    if (lane == 0) red[warp] = m;
    __syncthreads();
    m = red[lane & 7];
#pragma unroll
    for (int s = 4; s > 0; s >>= 1) m = fmaxf(m, __shfl_xor_sync(~0u, m, s));

    v0.x = __expf(v0.x - m); v0.y = __expf(v0.y - m);
    v0.z = __expf(v0.z - m); v0.w = __expf(v0.w - m);
    v1.x = __expf(v1.x - m); v1.y = __expf(v1.y - m);
    v1.z = __expf(v1.z - m); v1.w = __expf(v1.w - m);

    float sum = (v0.x + v0.y) + (v0.z + v0.w) + (v1.x + v1.y) + (v1.z + v1.w);
#pragma unroll
    for (int s = 16; s > 0; s >>= 1) sum += __shfl_xor_sync(~0u, sum, s);
    __syncthreads();
    if (lane == 0) red[warp] = sum;
    __syncthreads();
    sum = red[lane & 7];
#pragma unroll
    for (int s = 4; s > 0; s >>= 1) sum += __shfl_xor_sync(~0u, sum, s);

    float inv = 1.f / sum;
    v0.x *= inv; v0.y *= inv; v0.z *= inv; v0.w *= inv;
    v1.x *= inv; v1.y *= inv; v1.z *= inv; v1.w *= inv;
    p[tid] = v0;
    p[tid + 256] = v1;
}

// ---------------------------------------------------------------------------
// ctx = attn[S,S] @ Vh[S,64]; merged-head output [B*S, 1024].
// CTA 128m x 64n, BK=32 double-buffered. 8 warps (4m x 2n), warp 32x32.
// Dynamic smem: 2*128*36 + 2*64*36 floats.
// ---------------------------------------------------------------------------
__global__ __launch_bounds__(256, 2) void ctx_kernel(
    const float* __restrict__ attn, const float* __restrict__ Vh,
    float* __restrict__ ctx)
{
    extern __shared__ float sm[];
    float (*As)[128][36] = (float(*)[128][36])sm;                    // [buf][m][k]
    float (*Bs)[64][36]  = (float(*)[64][36])(sm + 2 * 128 * 36);    // [buf][n][k]

    const int bh = blockIdx.y;
    const float* A = attn + (size_t)bh * S_ * S_;
    const float* Bm = Vh + (size_t)bh * S_ * DEPTH_;
    const int b = bh >> 4, h = bh & 15;

    const int tid = threadIdx.x, lane = tid & 31, wid = tid >> 5;
    const int wm = wid & 3, wn = wid >> 2;
    const int row0 = blockIdx.x * 128;

    const int far = tid >> 3, fac = (tid & 7) * 4;    // A: rows far, far+64? (far 0..31? no: idx based)
    const int fvk = tid >> 4, fvn = (tid & 15) * 4;   // V: k-rows fvk, fvk+16

    float acc[2][4][4];
#pragma unroll
    for (int mi = 0; mi < 2; mi++)
#pragma unroll
        for (int ni = 0; ni < 4; ni++)
#pragma unroll
            for (int t = 0; t < 4; t++) acc[mi][ni][t] = 0.f;

    float4 pa[4], pv[2];
#pragma unroll
    for (int t = 0; t < 4; t++) {
        int idx = tid + t * 256;
        int r = idx >> 3, cc = (idx & 7) * 4;
        pa[t] = *(const float4*)(A + (size_t)(row0 + r) * S_ + cc);
    }
#pragma unroll
    for (int t = 0; t < 2; t++) {
        int idx = tid + t * 256;
        int kr = idx >> 4, nn = (idx & 15) * 4;
        pv[t] = *(const float4*)(Bm + (size_t)kr * DEPTH_ + nn);
    }
#pragma unroll
    for (int t = 0; t < 4; t++) {
        int idx = tid + t * 256;
        int r = idx >> 3, cc = (idx & 7) * 4;
        float* d = &As[0][r][cc];
        d[0] = f2tf(pa[t].x); d[1] = f2tf(pa[t].y); d[2] = f2tf(pa[t].z); d[3] = f2tf(pa[t].w);
    }
#pragma unroll
    for (int t = 0; t < 2; t++) {
        int idx = tid + t * 256;
        int kr = idx >> 4, nn = (idx & 15) * 4;
        Bs[0][nn + 0][kr] = f2tf(pv[t].x);
        Bs[0][nn + 1][kr] = f2tf(pv[t].y);
        Bs[0][nn + 2][kr] = f2tf(pv[t].z);
        Bs[0][nn + 3][kr] = f2tf(pv[t].w);
    }
    __syncthreads();

    const int nc = S_ / 32;   // 64
    for (int c = 0; c < nc; c++) {
        const int cur = c & 1;
        if (c + 1 < nc) {
            const int k0 = (c + 1) * 32;
#pragma unroll
            for (int t = 0; t < 4; t++) {
                int idx = tid + t * 256;
                int r = idx >> 3, cc = (idx & 7) * 4;
                pa[t] = *(const float4*)(A + (size_t)(row0 + r) * S_ + k0 + cc);
            }
#pragma unroll
            for (int t = 0; t < 2; t++) {
                int idx = tid + t * 256;
                int kr = idx >> 4, nn = (idx & 15) * 4;
                pv[t] = *(const float4*)(Bm + (size_t)(k0 + kr) * DEPTH_ + nn);
            }
        }
#pragma unroll
        for (int ks = 0; ks < 4; ks++) {
            unsigned af[2][4], bf[4][2];
#pragma unroll
            for (int mi = 0; mi < 2; mi++) {
                const float* p = &As[cur][wm * 32 + mi * 16 + (lane >> 2)][ks * 8 + (lane & 3)];
                af[mi][0] = U(p[0]); af[mi][1] = U(p[8 * 36]);
                af[mi][2] = U(p[4]); af[mi][3] = U(p[8 * 36 + 4]);
            }
#pragma unroll
            for (int ni = 0; ni < 4; ni++) {
                const float* p = &Bs[cur][wn * 32 + ni * 8 + (lane >> 2)][ks * 8 + (lane & 3)];
                bf[ni][0] = U(p[0]); bf[ni][1] = U(p[4]);
            }
#pragma unroll
            for (int mi = 0; mi < 2; mi++)
#pragma unroll
                for (int ni = 0; ni < 4; ni++)
                    mma_tf32(acc[mi][ni][0], acc[mi][ni][1], acc[mi][ni][2], acc[mi][ni][3],
                             af[mi][0], af[mi][1], af[mi][2], af[mi][3],
                             bf[ni][0], bf[ni][1]);
        }
        if (c + 1 < nc) {
            const int nxt = 1 - cur;
#pragma unroll
            for (int t = 0; t < 4; t++) {
                int idx = tid + t * 256;
                int r = idx >> 3, cc = (idx & 7) * 4;
                float* d = &As[nxt][r][cc];
                d[0] = f2tf(pa[t].x); d[1] = f2tf(pa[t].y); d[2] = f2tf(pa[t].z); d[3] = f2tf(pa[t].w);
            }
#pragma unroll
            for (int t = 0; t < 2; t++) {
                int idx = tid + t * 256;
                int kr = idx >> 4, nn = (idx & 15) * 4;
                Bs[nxt][nn + 0][kr] = f2tf(pv[t].x);
                Bs[nxt][nn + 1][kr] = f2tf(pv[t].y);
                Bs[nxt][nn + 2][kr] = f2tf(pv[t].z);
                Bs[nxt][nn + 3][kr] = f2tf(pv[t].w);
            }
        }
        __syncthreads();
    }

#pragma unroll
    for (int mi = 0; mi < 2; mi++) {
#pragma unroll
        for (int ni = 0; ni < 4; ni++) {
            int s = row0 + wm * 32 + mi * 16 + (lane >> 2);
            int cc = wn * 32 + ni * 8 + (lane & 3) * 2;
            float* dst = ctx + ((size_t)(b * S_ + s)) * D_ + h * DEPTH_ + cc;
            *(float2*)dst = make_float2(acc[mi][ni][0], acc[mi][ni][1]);
            *(float2*)(dst + 8 * D_) = make_float2(acc[mi][ni][2], acc[mi][ni][3]);
        }
    }
}

// ---------------------------------------------------------------------------
extern "C" void kernel_launch(void* const* d_in, const int* in_sizes, int n_in,
                              void* d_out, int out_size)
{
    const float* q    = (const float*)d_in[0];
    const float* k    = (const float*)d_in[1];
    const float* v    = (const float*)d_in[2];
    const float* mask = (const float*)d_in[3];
    const float* wq   = (const float*)d_in[4];
    const float* bq   = (const float*)d_in[5];
    const float* wk   = (const float*)d_in[6];
    const float* bk   = (const float*)d_in[7];
    const float* wv   = (const float*)d_in[8];
    const float* bv   = (const float*)d_in[9];
    const float* wo   = (const float*)d_in[10];
    const float* bo   = (const float*)d_in[11];

    float* out = (float*)d_out;

    float* attn;
    if ((size_t)out_size >= (size_t)OUT_ELEMS + ATTN_ELEMS) {
        attn = out + OUT_ELEMS;
    } else {
        cudaGetSymbolAddress((void**)&attn, g_attn_scratch);
    }

    float *Qh, *Kh, *Vh, *ctx;
    cudaGetSymbolAddress((void**)&Qh, g_Qh);
    cudaGetSymbolAddress((void**)&Kh, g_Kh);
    cudaGetSymbolAddress((void**)&Vh, g_Vh);
    cudaGetSymbolAddress((void**)&ctx, g_ctx);

    const int logitsSmem = 2 * 128 * 68 * sizeof(float);               // 69632
    const int ctxSmem = (2 * 128 * 36 + 2 * 64 * 36) * sizeof(float);  // 55296
    cudaFuncSetAttribute(logits_kernel, cudaFuncAttributeMaxDynamicSharedMemorySize, logitsSmem);
    cudaFuncSetAttribute(ctx_kernel, cudaFuncAttributeMaxDynamicSharedMemorySize, ctxSmem);

    dim3 projGrid(D_ / 128, M_ / 128);            // (8, 32)
    proj_kernel<<<projGrid, 256>>>(q, wq, bq, Qh, 1);
    proj_kernel<<<projGrid, 256>>>(k, wk, bk, Kh, 1);
    proj_kernel<<<projGrid, 256>>>(v, wv, bv, Vh, 1);

    dim3 logitsGrid(S_ / 128, S_ / 128, BH_);     // (16, 16, 32)
    logits_kernel<<<logitsGrid, 256, logitsSmem>>>(Qh, Kh, mask, attn);

    softmax_kernel<<<BH_ * S_, 256>>>(attn);      // 65536 rows

    dim3 ctxGrid(S_ / 128, BH_);                  // (16, 32)
    ctx_kernel<<<ctxGrid, 256, ctxSmem>>>(attn, Vh, ctx);

    proj_kernel<<<projGrid, 256>>>(ctx, wo, bo, out, 0);
}